// round 2
// baseline (speedup 1.0000x reference)
#include <cuda_runtime.h>
#include <math.h>

#define EDIM 1024
#define NH   16
#define HD   64
#define BATCH 4
#define SEQ  1024
#define MTOT (BATCH*SEQ)      // 4096
#define NREL (2*SEQ - 1)      // 2047

// ---- scratch (device globals: no allocation allowed in kernel_launch) ----
__device__ float g_Q[MTOT*EDIM];
__device__ float g_K[MTOT*EDIM];
__device__ float g_V[MTOT*EDIM];
__device__ float g_ctx[MTOT*EDIM];
__device__ float g_Rk[NREL*HD];

// ============================================================
// GEMM: C[M,N] = A[M,K] @ W[N,K]^T + bias[N]
// Both operands K-major (row-major, K contiguous). 128x128x8 tiles,
// 256 threads, 8x8 register tile per thread.
// M,N divisible by 128; K divisible by 8 (true for all calls here).
// ============================================================
__global__ __launch_bounds__(256) void gemm_bias_nt(
    const float* __restrict__ A, const float* __restrict__ W,
    const float* __restrict__ bias, float* __restrict__ C,
    int M, int N, int K)
{
    __shared__ float As[8][128];
    __shared__ float Bs[8][128];
    const int tid = threadIdx.x;
    const int tx = tid & 15, ty = tid >> 4;
    const int bm = blockIdx.y << 7, bn = blockIdx.x << 7;
    const int lrow = tid >> 1;          // 0..127
    const int lk4  = (tid & 1) << 2;    // 0 or 4

    const float* Ap = A + (size_t)(bm + lrow) * K + lk4;
    const float* Wp = W + (size_t)(bn + lrow) * K + lk4;

    float acc[8][8];
#pragma unroll
    for (int i = 0; i < 8; i++)
#pragma unroll
        for (int j = 0; j < 8; j++) acc[i][j] = 0.f;

    for (int k0 = 0; k0 < K; k0 += 8) {
        float4 av = *(const float4*)(Ap + k0);
        float4 wv = *(const float4*)(Wp + k0);
        __syncthreads();
        As[lk4+0][lrow] = av.x; As[lk4+1][lrow] = av.y;
        As[lk4+2][lrow] = av.z; As[lk4+3][lrow] = av.w;
        Bs[lk4+0][lrow] = wv.x; Bs[lk4+1][lrow] = wv.y;
        Bs[lk4+2][lrow] = wv.z; Bs[lk4+3][lrow] = wv.w;
        __syncthreads();
#pragma unroll
        for (int k = 0; k < 8; k++) {
            float a[8], b[8];
            *(float4*)&a[0] = *(const float4*)&As[k][ty << 3];
            *(float4*)&a[4] = *(const float4*)&As[k][(ty << 3) + 4];
            *(float4*)&b[0] = *(const float4*)&Bs[k][tx << 3];
            *(float4*)&b[4] = *(const float4*)&Bs[k][(tx << 3) + 4];
#pragma unroll
            for (int i = 0; i < 8; i++)
#pragma unroll
                for (int j = 0; j < 8; j++)
                    acc[i][j] += a[i] * b[j];
        }
    }

#pragma unroll
    for (int i = 0; i < 8; i++) {
        int row = bm + (ty << 3) + i;
#pragma unroll
        for (int j = 0; j < 8; j += 4) {
            int col = bn + (tx << 3) + j;
            float4 o;
            o.x = acc[i][j+0] + bias[col+0];
            o.y = acc[i][j+1] + bias[col+1];
            o.z = acc[i][j+2] + bias[col+2];
            o.w = acc[i][j+3] + bias[col+3];
            *(float4*)(C + (size_t)row * N + col) = o;
        }
    }
}

// ============================================================
// Rel projection: Rk[r][d] = sum_k rel_emb[r][k] * Wp[d][k]
// (start = MAX_SEQ_LEN - Lk = 0, so the full [2047,64] table is used)
// ============================================================
__global__ __launch_bounds__(64) void relproj_kernel(
    const float* __restrict__ rel_emb, const float* __restrict__ Wp,
    float* __restrict__ Rk)
{
    __shared__ float sW[HD*HD];
    __shared__ float sR[HD];
    const int tid = threadIdx.x;   // 0..63 = output dim d
    for (int i = tid; i < HD*HD; i += 64) sW[i] = Wp[i];
    const int r = blockIdx.x;
    sR[tid] = rel_emb[(size_t)r*HD + tid];
    __syncthreads();
    float acc = 0.f;
#pragma unroll 8
    for (int k = 0; k < HD; k++) acc += sR[k] * sW[tid*HD + k];
    Rk[(size_t)r*HD + tid] = acc;
}

// ============================================================
// Flash attention with fused relative scores.
// S[i,j] = scale * sum_d Q[i,d] * (K[j,d] + Rk[j-i+SEQ-1, d])
// Tiles: 64 query rows x 64 key cols, 256 threads (16x16 grid of 4x4 frags).
// Q/K/V/ctx layout: [B, L, H, D] flattened = [MTOT, EDIM] row-major.
// ============================================================
#define FBM 64
#define FBN 64
#define FLASH_SMEM ((3*64*65 + 64*64 + 64*128) * 4)   // 99072 bytes

__global__ __launch_bounds__(256) void flash_rel_kernel(
    const float* __restrict__ Q, const float* __restrict__ K,
    const float* __restrict__ V, const unsigned char* __restrict__ mask,
    const float* __restrict__ Rk, float* __restrict__ O)
{
    extern __shared__ float sm[];
    float* QsT = sm;                 // [64 d][65]  (transposed, padded)
    float* KsT = QsT + 64*65;        // [64 d][65]
    float* PsT = KsT + 64*65;        // [64 j][65]  (P transposed)
    float* Vs  = PsT + 64*65;        // [64 j][64]  row-major
    float* RkT = Vs  + 64*64;        // [64 d][128] band, idx 0..126

    const int tid = threadIdx.x;
    const int tx = tid & 15, ty = tid >> 4;
    const int b = blockIdx.z, h = blockIdx.y;
    const int i0 = blockIdx.x * FBM;
    const float scale = 0.125f;      // 1/sqrt(64)

    // load Q tile (transposed into smem)
    const float* Qbase = Q + ((size_t)(b*SEQ + i0)) * EDIM + h*HD;
    for (int e = tid; e < 64*16; e += 256) {
        int row = e >> 4;
        int d4  = (e & 15) << 2;
        float4 q = *(const float4*)(Qbase + (size_t)row*EDIM + d4);
        QsT[(d4+0)*65 + row] = q.x;
        QsT[(d4+1)*65 + row] = q.y;
        QsT[(d4+2)*65 + row] = q.z;
        QsT[(d4+3)*65 + row] = q.w;
    }

    float m_i[4], l_i[4], oacc[4][4];
#pragma unroll
    for (int r = 0; r < 4; r++) {
        m_i[r] = -INFINITY; l_i[r] = 0.f;
#pragma unroll
        for (int c = 0; c < 4; c++) oacc[r][c] = 0.f;
    }

    const int base_idx = 63 + (tx << 2) - (ty << 2);   // in [3,123]

    for (int kt = 0; kt < SEQ/FBN; kt++) {
        const int j0 = kt * FBN;
        __syncthreads();   // prior-iteration PV reads done before overwrite

        // load K (transposed) and V (row-major) tiles
        const float* Kbase = K + ((size_t)(b*SEQ + j0)) * EDIM + h*HD;
        const float* Vbase = V + ((size_t)(b*SEQ + j0)) * EDIM + h*HD;
        for (int e = tid; e < 64*16; e += 256) {
            int row = e >> 4;
            int d4  = (e & 15) << 2;
            float4 kv = *(const float4*)(Kbase + (size_t)row*EDIM + d4);
            KsT[(d4+0)*65 + row] = kv.x;
            KsT[(d4+1)*65 + row] = kv.y;
            KsT[(d4+2)*65 + row] = kv.z;
            KsT[(d4+3)*65 + row] = kv.w;
            float4 vv = *(const float4*)(Vbase + (size_t)row*EDIM + d4);
            *(float4*)(Vs + row*64 + d4) = vv;
        }
        // load Rk band: rows r0-63 .. r0+63 (always in range [0,2046])
        const int r0 = j0 - i0 + (SEQ - 1);
        for (int e = tid; e < 127*16; e += 256) {
            int idx = e >> 4;
            int d4  = (e & 15) << 2;
            float4 rv = *(const float4*)(Rk + (size_t)(r0 - 63 + idx)*HD + d4);
            RkT[(d4+0)*128 + idx] = rv.x;
            RkT[(d4+1)*128 + idx] = rv.y;
            RkT[(d4+2)*128 + idx] = rv.z;
            RkT[(d4+3)*128 + idx] = rv.w;
        }
        __syncthreads();

        // S = Q (K + Rk_band)^T — fused content + relative term
        float s[4][4];
#pragma unroll
        for (int r = 0; r < 4; r++)
#pragma unroll
            for (int c = 0; c < 4; c++) s[r][c] = 0.f;

#pragma unroll 4
        for (int d = 0; d < 64; d++) {
            float a[4], bb[4], rk[7];
#pragma unroll
            for (int r = 0; r < 4; r++) a[r]  = QsT[d*65 + (ty << 2) + r];
#pragma unroll
            for (int c = 0; c < 4; c++) bb[c] = KsT[d*65 + (tx << 2) + c];
#pragma unroll
            for (int t = 0; t < 7; t++) rk[t] = RkT[d*128 + base_idx - 3 + t];
#pragma unroll
            for (int r = 0; r < 4; r++)
#pragma unroll
                for (int c = 0; c < 4; c++)
                    s[r][c] += a[r] * (bb[c] + rk[c - r + 3]);
        }

        // scale + mask
        const unsigned char* mrow = mask + (size_t)b*SEQ*SEQ
                                  + (size_t)(i0 + (ty << 2))*SEQ + j0 + (tx << 2);
#pragma unroll
        for (int r = 0; r < 4; r++) {
            uchar4 mk = *(const uchar4*)(mrow + (size_t)r*SEQ);
            s[r][0] = mk.x ? -INFINITY : s[r][0]*scale;
            s[r][1] = mk.y ? -INFINITY : s[r][1]*scale;
            s[r][2] = mk.z ? -INFINITY : s[r][2]*scale;
            s[r][3] = mk.w ? -INFINITY : s[r][3]*scale;
        }

        // online softmax (row reductions across the 16 tx lanes)
#pragma unroll
        for (int r = 0; r < 4; r++) {
            float mx = fmaxf(fmaxf(s[r][0], s[r][1]), fmaxf(s[r][2], s[r][3]));
#pragma unroll
            for (int off = 8; off >= 1; off >>= 1)
                mx = fmaxf(mx, __shfl_xor_sync(0xffffffffu, mx, off));
            float mnew  = fmaxf(m_i[r], mx);
            float alpha = __expf(m_i[r] - mnew);
            s[r][0] = __expf(s[r][0] - mnew);
            s[r][1] = __expf(s[r][1] - mnew);
            s[r][2] = __expf(s[r][2] - mnew);
            s[r][3] = __expf(s[r][3] - mnew);
            float rs = s[r][0] + s[r][1] + s[r][2] + s[r][3];
#pragma unroll
            for (int off = 8; off >= 1; off >>= 1)
                rs += __shfl_xor_sync(0xffffffffu, rs, off);
            l_i[r] = l_i[r]*alpha + rs;
            m_i[r] = mnew;
#pragma unroll
            for (int c = 0; c < 4; c++) oacc[r][c] *= alpha;
        }

        // stage P (transposed) for the PV GEMM
#pragma unroll
        for (int r = 0; r < 4; r++)
#pragma unroll
            for (int c = 0; c < 4; c++)
                PsT[((tx << 2) + c)*65 + (ty << 2) + r] = s[r][c];
        __syncthreads();

        // O += P @ V
#pragma unroll 4
        for (int j = 0; j < 64; j++) {
            float pa[4], vb[4];
#pragma unroll
            for (int r = 0; r < 4; r++) pa[r] = PsT[j*65 + (ty << 2) + r];
#pragma unroll
            for (int c = 0; c < 4; c++) vb[c] = Vs[j*64 + (tx << 2) + c];
#pragma unroll
            for (int r = 0; r < 4; r++)
#pragma unroll
                for (int c = 0; c < 4; c++)
                    oacc[r][c] += pa[r] * vb[c];
        }
    }

    // epilogue: normalize, write ctx in [B,L,H,D] layout
    float* Obase = O + ((size_t)(b*SEQ + i0)) * EDIM + h*HD;
#pragma unroll
    for (int r = 0; r < 4; r++) {
        float inv = 1.f / l_i[r];
#pragma unroll
        for (int c = 0; c < 4; c++)
            Obase[(size_t)((ty << 2) + r)*EDIM + (tx << 2) + c] = oacc[r][c] * inv;
    }
}

// ============================================================
extern "C" void kernel_launch(void* const* d_in, const int* in_sizes, int n_in,
                              void* d_out, int out_size)
{
    const float* query = (const float*)d_in[0];
    const float* key_  = (const float*)d_in[1];
    const float* value = (const float*)d_in[2];
    const unsigned char* mask = (const unsigned char*)d_in[3];
    const float* Wq = (const float*)d_in[4];
    const float* bq = (const float*)d_in[5];
    const float* Wk = (const float*)d_in[6];
    const float* bk = (const float*)d_in[7];
    const float* Wv = (const float*)d_in[8];
    const float* bv = (const float*)d_in[9];
    const float* Wo = (const float*)d_in[10];
    const float* bo = (const float*)d_in[11];
    const float* rel_emb = (const float*)d_in[12];
    const float* Wp = (const float*)d_in[13];
    float* out = (float*)d_out;

    float *Qg, *Kg, *Vg, *Cg, *Rkg;
    cudaGetSymbolAddress((void**)&Qg,  g_Q);
    cudaGetSymbolAddress((void**)&Kg,  g_K);
    cudaGetSymbolAddress((void**)&Vg,  g_V);
    cudaGetSymbolAddress((void**)&Cg,  g_ctx);
    cudaGetSymbolAddress((void**)&Rkg, g_Rk);

    cudaFuncSetAttribute(flash_rel_kernel,
                         cudaFuncAttributeMaxDynamicSharedMemorySize, FLASH_SMEM);

    dim3 gblk(256);
    dim3 ggrid(EDIM/128, MTOT/128);   // (8, 32)

    gemm_bias_nt<<<ggrid, gblk>>>(query, Wq, bq, Qg, MTOT, EDIM, EDIM);
    gemm_bias_nt<<<ggrid, gblk>>>(key_,  Wk, bk, Kg, MTOT, EDIM, EDIM);
    gemm_bias_nt<<<ggrid, gblk>>>(value, Wv, bv, Vg, MTOT, EDIM, EDIM);
    relproj_kernel<<<NREL, 64>>>(rel_emb, Wp, Rkg);

    dim3 fgrid(SEQ/FBM, NH, BATCH);   // (16, 16, 4) = 1024 blocks
    flash_rel_kernel<<<fgrid, 256, FLASH_SMEM>>>(Qg, Kg, Vg, mask, Rkg, Cg);

    gemm_bias_nt<<<ggrid, gblk>>>(Cg, Wo, bo, out, MTOT, EDIM, EDIM);
}

// round 3
// speedup vs baseline: 1.4540x; 1.4540x over previous
#include <cuda_runtime.h>
#include <math.h>
#include <stdint.h>

#define EDIM 1024
#define NH   16
#define HD   64
#define BATCH 4
#define SEQ  1024
#define MTOT (BATCH*SEQ)      // 4096
#define NREL (2*SEQ - 1)      // 2047

// ---- scratch (device globals: no allocation allowed in kernel_launch) ----
__device__ float g_Q[MTOT*EDIM];
__device__ float g_K[MTOT*EDIM];
__device__ float g_V[MTOT*EDIM];
__device__ float g_ctx[MTOT*EDIM];
__device__ float g_Rk[NREL*HD];

__device__ __forceinline__ uint32_t f2tf32(float f) {
    uint32_t u;
    asm("cvt.rna.tf32.f32 %0, %1;" : "=r"(u) : "f"(f));
    return u;
}

// ============================================================
// TF32 tensor-core GEMM: C[M,N] = A[M,K] @ W[N,K]^T + bias[N]
// Both operands K-major. Block tile 128x128, k-tile 32, double-buffered.
// 8 warps in a 2(M) x 4(N) grid; each warp computes 64x32 via
// 4x4 grid of mma.sync.m16n8k8.tf32.
// Requires M%128==0, N%128==0, K%32==0.
// ============================================================
#define KC  32
#define PAD 36
#define GEMM_SMEM (2*2*128*PAD*4)   // 73728 bytes

__global__ __launch_bounds__(256) void gemm_tf32_nt(
    const float* __restrict__ A, const float* __restrict__ W,
    const float* __restrict__ bias, float* __restrict__ C,
    int M, int N, int K)
{
    extern __shared__ float smf[];
    uint32_t* As = (uint32_t*)smf;            // [2][128][PAD]
    uint32_t* Bs = As + 2*128*PAD;            // [2][128][PAD]

    const int tid  = threadIdx.x;
    const int lane = tid & 31;
    const int warp = tid >> 5;
    const int g    = lane >> 2;     // 0..7
    const int tig  = lane & 3;      // 0..3
    const int wm   = warp >> 2;     // 0..1
    const int wn   = warp & 3;      // 0..3
    const int bm   = blockIdx.y << 7;
    const int bn   = blockIdx.x << 7;

    // gmem load mapping: 4 float4 per thread per tile per operand
    const int r0 = tid >> 3;        // 0..31 (rows r0, r0+32, r0+64, r0+96)
    const int c4 = tid & 7;         // float4 column index 0..7

    const float* Ap = A + (size_t)(bm + r0) * K + (c4 << 2);
    const float* Wp = W + (size_t)(bn + r0) * K + (c4 << 2);

    float acc[4][4][4];
#pragma unroll
    for (int mi = 0; mi < 4; mi++)
#pragma unroll
        for (int ni = 0; ni < 4; ni++)
#pragma unroll
            for (int q = 0; q < 4; q++) acc[mi][ni][q] = 0.f;

    float4 ra[4], rw[4];
    const int nt = K / KC;

    // prologue: fetch tile 0
#pragma unroll
    for (int i = 0; i < 4; i++) {
        ra[i] = *(const float4*)(Ap + (size_t)(i*32) * K);
        rw[i] = *(const float4*)(Wp + (size_t)(i*32) * K);
    }
    {
        uint32_t* dA = As;
        uint32_t* dB = Bs;
#pragma unroll
        for (int i = 0; i < 4; i++) {
            int off = (r0 + i*32)*PAD + (c4 << 2);
            dA[off+0] = f2tf32(ra[i].x); dA[off+1] = f2tf32(ra[i].y);
            dA[off+2] = f2tf32(ra[i].z); dA[off+3] = f2tf32(ra[i].w);
            dB[off+0] = f2tf32(rw[i].x); dB[off+1] = f2tf32(rw[i].y);
            dB[off+2] = f2tf32(rw[i].z); dB[off+3] = f2tf32(rw[i].w);
        }
    }

    for (int kt = 0; kt < nt; kt++) {
        __syncthreads();
        // prefetch next tile into registers
        if (kt + 1 < nt) {
            const float* Ap2 = Ap + (size_t)(kt+1)*KC;
            const float* Wp2 = Wp + (size_t)(kt+1)*KC;
#pragma unroll
            for (int i = 0; i < 4; i++) {
                ra[i] = *(const float4*)(Ap2 + (size_t)(i*32) * K);
                rw[i] = *(const float4*)(Wp2 + (size_t)(i*32) * K);
            }
        }

        const uint32_t* cA = As + (kt & 1) * 128*PAD;
        const uint32_t* cB = Bs + (kt & 1) * 128*PAD;

#pragma unroll
        for (int kk = 0; kk < KC; kk += 8) {
            uint32_t af[4][4], bf[4][2];
#pragma unroll
            for (int mi = 0; mi < 4; mi++) {
                int r = (wm << 6) + (mi << 4);
                af[mi][0] = cA[(r + g    )*PAD + kk + tig    ];
                af[mi][1] = cA[(r + g + 8)*PAD + kk + tig    ];
                af[mi][2] = cA[(r + g    )*PAD + kk + tig + 4];
                af[mi][3] = cA[(r + g + 8)*PAD + kk + tig + 4];
            }
#pragma unroll
            for (int ni = 0; ni < 4; ni++) {
                int cn = (wn << 5) + (ni << 3);
                bf[ni][0] = cB[(cn + g)*PAD + kk + tig    ];
                bf[ni][1] = cB[(cn + g)*PAD + kk + tig + 4];
            }
#pragma unroll
            for (int mi = 0; mi < 4; mi++)
#pragma unroll
                for (int ni = 0; ni < 4; ni++) {
                    asm volatile(
                        "mma.sync.aligned.m16n8k8.row.col.f32.tf32.tf32.f32 "
                        "{%0,%1,%2,%3}, {%4,%5,%6,%7}, {%8,%9}, {%0,%1,%2,%3};"
                        : "+f"(acc[mi][ni][0]), "+f"(acc[mi][ni][1]),
                          "+f"(acc[mi][ni][2]), "+f"(acc[mi][ni][3])
                        : "r"(af[mi][0]), "r"(af[mi][1]),
                          "r"(af[mi][2]), "r"(af[mi][3]),
                          "r"(bf[ni][0]), "r"(bf[ni][1]));
                }
        }

        // stage next tile into the other buffer
        if (kt + 1 < nt) {
            uint32_t* dA = As + ((kt+1) & 1) * 128*PAD;
            uint32_t* dB = Bs + ((kt+1) & 1) * 128*PAD;
#pragma unroll
            for (int i = 0; i < 4; i++) {
                int off = (r0 + i*32)*PAD + (c4 << 2);
                dA[off+0] = f2tf32(ra[i].x); dA[off+1] = f2tf32(ra[i].y);
                dA[off+2] = f2tf32(ra[i].z); dA[off+3] = f2tf32(ra[i].w);
                dB[off+0] = f2tf32(rw[i].x); dB[off+1] = f2tf32(rw[i].y);
                dB[off+2] = f2tf32(rw[i].z); dB[off+3] = f2tf32(rw[i].w);
            }
        }
    }

    // epilogue: add bias, write fp32
#pragma unroll
    for (int mi = 0; mi < 4; mi++) {
        int row = bm + (wm << 6) + (mi << 4) + g;
#pragma unroll
        for (int ni = 0; ni < 4; ni++) {
            int col = bn + (wn << 5) + (ni << 3) + (tig << 1);
            float b0 = bias[col], b1 = bias[col + 1];
            float2 o0 = make_float2(acc[mi][ni][0] + b0, acc[mi][ni][1] + b1);
            float2 o1 = make_float2(acc[mi][ni][2] + b0, acc[mi][ni][3] + b1);
            *(float2*)(C + (size_t)row       * N + col) = o0;
            *(float2*)(C + (size_t)(row + 8) * N + col) = o1;
        }
    }
}

// ============================================================
// Rel projection: Rk[r][d] = sum_k rel_emb[r][k] * Wp[d][k]
// ============================================================
__global__ __launch_bounds__(64) void relproj_kernel(
    const float* __restrict__ rel_emb, const float* __restrict__ Wp,
    float* __restrict__ Rk)
{
    __shared__ float sW[HD*HD];
    __shared__ float sR[HD];
    const int tid = threadIdx.x;
    for (int i = tid; i < HD*HD; i += 64) sW[i] = Wp[i];
    const int r = blockIdx.x;
    sR[tid] = rel_emb[(size_t)r*HD + tid];
    __syncthreads();
    float acc = 0.f;
#pragma unroll 8
    for (int k = 0; k < HD; k++) acc += sR[k] * sW[tid*HD + k];
    Rk[(size_t)r*HD + tid] = acc;
}

// ============================================================
// Flash attention with fused relative scores (fp32, unchanged).
// ============================================================
#define FBM 64
#define FBN 64
#define FLASH_SMEM ((3*64*65 + 64*64 + 64*128) * 4)   // 99072 bytes

__global__ __launch_bounds__(256) void flash_rel_kernel(
    const float* __restrict__ Q, const float* __restrict__ K,
    const float* __restrict__ V, const unsigned char* __restrict__ mask,
    const float* __restrict__ Rk, float* __restrict__ O)
{
    extern __shared__ float sm[];
    float* QsT = sm;                 // [64 d][65]
    float* KsT = QsT + 64*65;        // [64 d][65]
    float* PsT = KsT + 64*65;        // [64 j][65]
    float* Vs  = PsT + 64*65;        // [64 j][64]
    float* RkT = Vs  + 64*64;        // [64 d][128]

    const int tid = threadIdx.x;
    const int tx = tid & 15, ty = tid >> 4;
    const int b = blockIdx.z, h = blockIdx.y;
    const int i0 = blockIdx.x * FBM;
    const float scale = 0.125f;

    const float* Qbase = Q + ((size_t)(b*SEQ + i0)) * EDIM + h*HD;
    for (int e = tid; e < 64*16; e += 256) {
        int row = e >> 4;
        int d4  = (e & 15) << 2;
        float4 q = *(const float4*)(Qbase + (size_t)row*EDIM + d4);
        QsT[(d4+0)*65 + row] = q.x;
        QsT[(d4+1)*65 + row] = q.y;
        QsT[(d4+2)*65 + row] = q.z;
        QsT[(d4+3)*65 + row] = q.w;
    }

    float m_i[4], l_i[4], oacc[4][4];
#pragma unroll
    for (int r = 0; r < 4; r++) {
        m_i[r] = -INFINITY; l_i[r] = 0.f;
#pragma unroll
        for (int c = 0; c < 4; c++) oacc[r][c] = 0.f;
    }

    const int base_idx = 63 + (tx << 2) - (ty << 2);

    for (int kt = 0; kt < SEQ/FBN; kt++) {
        const int j0 = kt * FBN;
        __syncthreads();

        const float* Kbase = K + ((size_t)(b*SEQ + j0)) * EDIM + h*HD;
        const float* Vbase = V + ((size_t)(b*SEQ + j0)) * EDIM + h*HD;
        for (int e = tid; e < 64*16; e += 256) {
            int row = e >> 4;
            int d4  = (e & 15) << 2;
            float4 kv = *(const float4*)(Kbase + (size_t)row*EDIM + d4);
            KsT[(d4+0)*65 + row] = kv.x;
            KsT[(d4+1)*65 + row] = kv.y;
            KsT[(d4+2)*65 + row] = kv.z;
            KsT[(d4+3)*65 + row] = kv.w;
            float4 vv = *(const float4*)(Vbase + (size_t)row*EDIM + d4);
            *(float4*)(Vs + row*64 + d4) = vv;
        }
        const int r0 = j0 - i0 + (SEQ - 1);
        for (int e = tid; e < 127*16; e += 256) {
            int idx = e >> 4;
            int d4  = (e & 15) << 2;
            float4 rv = *(const float4*)(Rk + (size_t)(r0 - 63 + idx)*HD + d4);
            RkT[(d4+0)*128 + idx] = rv.x;
            RkT[(d4+1)*128 + idx] = rv.y;
            RkT[(d4+2)*128 + idx] = rv.z;
            RkT[(d4+3)*128 + idx] = rv.w;
        }
        __syncthreads();

        float s[4][4];
#pragma unroll
        for (int r = 0; r < 4; r++)
#pragma unroll
            for (int c = 0; c < 4; c++) s[r][c] = 0.f;

#pragma unroll 4
        for (int d = 0; d < 64; d++) {
            float a[4], bb[4], rk[7];
#pragma unroll
            for (int r = 0; r < 4; r++) a[r]  = QsT[d*65 + (ty << 2) + r];
#pragma unroll
            for (int c = 0; c < 4; c++) bb[c] = KsT[d*65 + (tx << 2) + c];
#pragma unroll
            for (int t = 0; t < 7; t++) rk[t] = RkT[d*128 + base_idx - 3 + t];
#pragma unroll
            for (int r = 0; r < 4; r++)
#pragma unroll
                for (int c = 0; c < 4; c++)
                    s[r][c] += a[r] * (bb[c] + rk[c - r + 3]);
        }

        const unsigned char* mrow = mask + (size_t)b*SEQ*SEQ
                                  + (size_t)(i0 + (ty << 2))*SEQ + j0 + (tx << 2);
#pragma unroll
        for (int r = 0; r < 4; r++) {
            uchar4 mk = *(const uchar4*)(mrow + (size_t)r*SEQ);
            s[r][0] = mk.x ? -INFINITY : s[r][0]*scale;
            s[r][1] = mk.y ? -INFINITY : s[r][1]*scale;
            s[r][2] = mk.z ? -INFINITY : s[r][2]*scale;
            s[r][3] = mk.w ? -INFINITY : s[r][3]*scale;
        }

#pragma unroll
        for (int r = 0; r < 4; r++) {
            float mx = fmaxf(fmaxf(s[r][0], s[r][1]), fmaxf(s[r][2], s[r][3]));
#pragma unroll
            for (int off = 8; off >= 1; off >>= 1)
                mx = fmaxf(mx, __shfl_xor_sync(0xffffffffu, mx, off));
            float mnew  = fmaxf(m_i[r], mx);
            float alpha = __expf(m_i[r] - mnew);
            s[r][0] = __expf(s[r][0] - mnew);
            s[r][1] = __expf(s[r][1] - mnew);
            s[r][2] = __expf(s[r][2] - mnew);
            s[r][3] = __expf(s[r][3] - mnew);
            float rs = s[r][0] + s[r][1] + s[r][2] + s[r][3];
#pragma unroll
            for (int off = 8; off >= 1; off >>= 1)
                rs += __shfl_xor_sync(0xffffffffu, rs, off);
            l_i[r] = l_i[r]*alpha + rs;
            m_i[r] = mnew;
#pragma unroll
            for (int c = 0; c < 4; c++) oacc[r][c] *= alpha;
        }

#pragma unroll
        for (int r = 0; r < 4; r++)
#pragma unroll
            for (int c = 0; c < 4; c++)
                PsT[((tx << 2) + c)*65 + (ty << 2) + r] = s[r][c];
        __syncthreads();

#pragma unroll 4
        for (int j = 0; j < 64; j++) {
            float pa[4], vb[4];
#pragma unroll
            for (int r = 0; r < 4; r++) pa[r] = PsT[j*65 + (ty << 2) + r];
#pragma unroll
            for (int c = 0; c < 4; c++) vb[c] = Vs[j*64 + (tx << 2) + c];
#pragma unroll
            for (int r = 0; r < 4; r++)
#pragma unroll
                for (int c = 0; c < 4; c++)
                    oacc[r][c] += pa[r] * vb[c];
        }
    }

    float* Obase = O + ((size_t)(b*SEQ + i0)) * EDIM + h*HD;
#pragma unroll
    for (int r = 0; r < 4; r++) {
        float inv = 1.f / l_i[r];
#pragma unroll
        for (int c = 0; c < 4; c++)
            Obase[(size_t)((ty << 2) + r)*EDIM + (tx << 2) + c] = oacc[r][c] * inv;
    }
}

// ============================================================
extern "C" void kernel_launch(void* const* d_in, const int* in_sizes, int n_in,
                              void* d_out, int out_size)
{
    const float* query = (const float*)d_in[0];
    const float* key_  = (const float*)d_in[1];
    const float* value = (const float*)d_in[2];
    const unsigned char* mask = (const unsigned char*)d_in[3];
    const float* Wq = (const float*)d_in[4];
    const float* bq = (const float*)d_in[5];
    const float* Wk = (const float*)d_in[6];
    const float* bk = (const float*)d_in[7];
    const float* Wv = (const float*)d_in[8];
    const float* bv = (const float*)d_in[9];
    const float* Wo = (const float*)d_in[10];
    const float* bo = (const float*)d_in[11];
    const float* rel_emb = (const float*)d_in[12];
    const float* Wp = (const float*)d_in[13];
    float* out = (float*)d_out;

    float *Qg, *Kg, *Vg, *Cg, *Rkg;
    cudaGetSymbolAddress((void**)&Qg,  g_Q);
    cudaGetSymbolAddress((void**)&Kg,  g_K);
    cudaGetSymbolAddress((void**)&Vg,  g_V);
    cudaGetSymbolAddress((void**)&Cg,  g_ctx);
    cudaGetSymbolAddress((void**)&Rkg, g_Rk);

    cudaFuncSetAttribute(flash_rel_kernel,
                         cudaFuncAttributeMaxDynamicSharedMemorySize, FLASH_SMEM);
    cudaFuncSetAttribute(gemm_tf32_nt,
                         cudaFuncAttributeMaxDynamicSharedMemorySize, GEMM_SMEM);

    dim3 gblk(256);
    dim3 ggrid(EDIM/128, MTOT/128);   // (8, 32)

    gemm_tf32_nt<<<ggrid, gblk, GEMM_SMEM>>>(query, Wq, bq, Qg, MTOT, EDIM, EDIM);
    gemm_tf32_nt<<<ggrid, gblk, GEMM_SMEM>>>(key_,  Wk, bk, Kg, MTOT, EDIM, EDIM);
    gemm_tf32_nt<<<ggrid, gblk, GEMM_SMEM>>>(value, Wv, bv, Vg, MTOT, EDIM, EDIM);
    relproj_kernel<<<NREL, 64>>>(rel_emb, Wp, Rkg);

    dim3 fgrid(SEQ/FBM, NH, BATCH);   // (16, 16, 4)
    flash_rel_kernel<<<fgrid, 256, FLASH_SMEM>>>(Qg, Kg, Vg, mask, Rkg, Cg);

    gemm_tf32_nt<<<ggrid, gblk, GEMM_SMEM>>>(Cg, Wo, bo, out, MTOT, EDIM, EDIM);
}